// round 9
// baseline (speedup 1.0000x reference)
#include <cuda_runtime.h>
#include <cuda_bf16.h>
#include <cstdint>

// ---------------------------------------------------------------------------
// GatedAttentionUnit: S=2048, B=4, E=1024, Z=128, H=2048
// R9: double-buffered overlap (MMA(c) || cvt+STS(c+1)) like R7, but with
//     32-fp32 K-chunks so total smem = 73.7 KB ~= R6's proven footprint
//     (R7/R8's 139 KB opt-in is the only launch-visible delta vs passing R6
//     and is the prime suspect in the 4x container failures).
//     Math unchanged: mma.sync bf16 split-2, 3 passes hh+hl+lh, fp32 accum.
// ---------------------------------------------------------------------------

#define S_LEN 2048
#define BSZ 4
#define EDIM 1024
#define ZDIM 128
#define HDIM 2048
#define NTHREADS 256

// smem tile: 128 rows x 64 bf16 (hi 32 | lo 32) = 32 words + pad
// ROW_W = 36 (36 % 32 == 4 -> fragment LDS bank == lane -> conflict-free)
#define ROW_W 36
#define TILE_W (128 * ROW_W)                // 4608 words per tile
#define BUF_W (2 * TILE_W)                  // A + B, one stage (36864 B)
#define SMEM_DYN_BYTES (2 * BUF_W * 4)      // two stages = 73728 B

// Scratch (device globals: allocation-free per harness rules)
__device__ float d_u   [(size_t)S_LEN * BSZ * HDIM];
__device__ float d_vT  [(size_t)BSZ * HDIM * S_LEN];
__device__ float d_q   [(size_t)BSZ * S_LEN * ZDIM];
__device__ float d_kk  [(size_t)BSZ * S_LEN * ZDIM];
__device__ float d_attn[(size_t)BSZ * S_LEN * S_LEN];
__device__ float d_g   [(size_t)S_LEN * BSZ * HDIM];

// ---------------------------------------------------------------------------
__device__ __forceinline__ void mma16816(float* d, const uint32_t* a, const uint32_t* b) {
    asm volatile(
        "mma.sync.aligned.m16n8k16.row.col.f32.bf16.bf16.f32 "
        "{%0,%1,%2,%3}, {%4,%5,%6,%7}, {%8,%9}, {%0,%1,%2,%3};"
        : "+f"(d[0]), "+f"(d[1]), "+f"(d[2]), "+f"(d[3])
        : "r"(a[0]), "r"(a[1]), "r"(a[2]), "r"(a[3]), "r"(b[0]), "r"(b[1]));
}

__device__ __forceinline__ uint32_t pack_hi(float f0, float f1) {
    __nv_bfloat16 h0 = __float2bfloat16_rn(f0);
    __nv_bfloat16 h1 = __float2bfloat16_rn(f1);
    return (uint32_t)__bfloat16_as_ushort(h0) | ((uint32_t)__bfloat16_as_ushort(h1) << 16);
}
__device__ __forceinline__ uint32_t pack_lo(float f0, float f1) {
    __nv_bfloat16 h0 = __float2bfloat16_rn(f0);
    __nv_bfloat16 h1 = __float2bfloat16_rn(f1);
    __nv_bfloat16 l0 = __float2bfloat16_rn(f0 - __bfloat162float(h0));
    __nv_bfloat16 l1 = __float2bfloat16_rn(f1 - __bfloat162float(h1));
    return (uint32_t)__bfloat16_as_ushort(l0) | ((uint32_t)__bfloat16_as_ushort(l1) << 16);
}

// Load one 32-fp32-wide K chunk of A and B tiles into registers (4+4 float4)
__device__ __forceinline__ void load_chunk(
    const float* __restrict__ A, int lda,
    const float* __restrict__ B, int ldb, int c, float4 fs[8])
{
    const int tid = threadIdx.x;
#pragma unroll
    for (int u = 0; u < 2; ++u) {
        int idx = u * 256 + tid;
        int row = idx >> 2, grp = idx & 3;
        const float* pa = A + (size_t)row * lda + c * 32 + grp * 8;
        fs[u * 2 + 0] = *(const float4*)pa;
        fs[u * 2 + 1] = *(const float4*)(pa + 4);
        const float* pb = B + (size_t)row * ldb + c * 32 + grp * 8;
        fs[u * 2 + 4] = *(const float4*)pb;
        fs[u * 2 + 5] = *(const float4*)(pb + 4);
    }
}

// Convert registers -> [hi|lo] bf16 smem tiles (Aw/Bw of ONE stage)
__device__ __forceinline__ void store_chunk(const float4 fs[8],
                                            uint32_t* Aw, uint32_t* Bw)
{
    const int tid = threadIdx.x;
#pragma unroll
    for (int u = 0; u < 2; ++u) {
        int idx = u * 256 + tid;
        int row = idx >> 2, grp = idx & 3;
        const float4 a0 = fs[u * 2 + 0], a1 = fs[u * 2 + 1];
        const float4 b0 = fs[u * 2 + 4], b1 = fs[u * 2 + 5];
        uint32_t* ah = Aw + row * ROW_W + grp * 4;
        *(uint4*)ah = make_uint4(pack_hi(a0.x, a0.y), pack_hi(a0.z, a0.w),
                                 pack_hi(a1.x, a1.y), pack_hi(a1.z, a1.w));
        *(uint4*)(ah + 16) = make_uint4(pack_lo(a0.x, a0.y), pack_lo(a0.z, a0.w),
                                        pack_lo(a1.x, a1.y), pack_lo(a1.z, a1.w));
        uint32_t* bh = Bw + row * ROW_W + grp * 4;
        *(uint4*)bh = make_uint4(pack_hi(b0.x, b0.y), pack_hi(b0.z, b0.w),
                                 pack_hi(b1.x, b1.y), pack_hi(b1.z, b1.w));
        *(uint4*)(bh + 16) = make_uint4(pack_lo(b0.x, b0.y), pack_lo(b0.z, b0.w),
                                        pack_lo(b1.x, b1.y), pack_lo(b1.z, b1.w));
    }
}

// ---------------------------------------------------------------------------
// Core GEMM: acc(128x128) = A(128xK) * B(128xK)^T, fp32 in, fp32 accum.
// Warp grid 2(M) x 4(N); per-warp 64x32 via 4x4 m16n8k16 tiles.
// Split-2 via 3 runtime passes: (Ahi,Bhi), (Ahi,Blo), (Alo,Bhi).
// Double-buffered: MMA(c) overlaps pack+store of chunk c+1.
// nChunks counts 32-fp32 chunks (K/32).
// ---------------------------------------------------------------------------
extern __shared__ uint32_t smw[];

__device__ __forceinline__ void mma_gemm(
    const float* __restrict__ A, int lda,
    const float* __restrict__ B, int ldb,
    int nChunks, float acc[4][4][4])
{
    const int tid = threadIdx.x;
    const int lane = tid & 31, wid = tid >> 5;
    const int g = lane >> 2, tg = lane & 3;
    const int wm = wid & 1, wn = wid >> 1;
    const int arow = wm * 64 + g;
    const int brow = wn * 32 + g;

    float4 fs[8];
    // Prologue: stage chunk 0 into buffer 0
    load_chunk(A, lda, B, ldb, 0, fs);
    store_chunk(fs, smw, smw + TILE_W);
    __syncthreads();

    for (int c = 0; c < nChunks; ++c) {
        uint32_t* Aw = smw + (c & 1) * BUF_W;
        uint32_t* Bw = Aw + TILE_W;
        const bool more = (c + 1 < nChunks);
        if (more) load_chunk(A, lda, B, ldb, c + 1, fs);

        // 3 passes x 2 k-steps of 16: hi*hi, hi*lo, lo*hi  (reads buf c&1)
#pragma unroll 1
        for (int p = 0; p < 3; ++p) {
            const int aO = (p == 2) ? 16 : 0;
            const int bO = (p == 1) ? 16 : 0;
#pragma unroll
            for (int ks = 0; ks < 2; ++ks) {
                uint32_t av[4][4], bv[4][2];
#pragma unroll
                for (int mi = 0; mi < 4; ++mi) {
                    const uint32_t* pA = Aw + (arow + mi * 16) * ROW_W + aO + ks * 8 + tg;
                    av[mi][0] = pA[0];
                    av[mi][1] = pA[8 * ROW_W];
                    av[mi][2] = pA[4];
                    av[mi][3] = pA[8 * ROW_W + 4];
                }
#pragma unroll
                for (int ni = 0; ni < 4; ++ni) {
                    const uint32_t* pB = Bw + (brow + ni * 8) * ROW_W + bO + ks * 8 + tg;
                    bv[ni][0] = pB[0];
                    bv[ni][1] = pB[4];
                }
#pragma unroll
                for (int mi = 0; mi < 4; ++mi)
#pragma unroll
                    for (int ni = 0; ni < 4; ++ni)
                        mma16816(acc[mi][ni], av[mi], bv[ni]);
            }
        }

        // Stage chunk c+1 into the OTHER buffer; overlaps with HMMA drain.
        if (more) {
            uint32_t* Aw2 = smw + ((c + 1) & 1) * BUF_W;
            store_chunk(fs, Aw2, Aw2 + TILE_W);
        }
        __syncthreads();
    }
}

__device__ __forceinline__ float silu(float v) { return v / (1.0f + __expf(-v)); }

// Per-thread element coordinates inside the 128x128 tile:
//   r = wm*64 + mi*16 + g + (e>=2 ? 8 : 0)
//   c = wn*32 + ni*8 + tg*2 + (e&1)

// ---------------------------------------------------------------------------
// K1: proj = silu(x @ Wp^T + bp); split into u / vT / q / k
// ---------------------------------------------------------------------------
__global__ void __launch_bounds__(NTHREADS, 1)
k_proj_t(const float* __restrict__ X, const float* __restrict__ W,
         const float* __restrict__ pb, const float* __restrict__ gamma,
         const float* __restrict__ beta)
{
    const int bx = blockIdx.x, by = blockIdx.y;
    float acc[4][4][4] = {};
    mma_gemm(X + (size_t)by * 128 * EDIM, EDIM,
             W + (size_t)bx * 128 * EDIM, EDIM, EDIM / 32, acc);

    const int lane = threadIdx.x & 31, wid = threadIdx.x >> 5;
    const int g = lane >> 2, tg = lane & 3;
    const int wm = wid & 1, wn = wid >> 1;
#pragma unroll
    for (int mi = 0; mi < 4; ++mi) {
#pragma unroll
        for (int ni = 0; ni < 4; ++ni) {
#pragma unroll
            for (int e = 0; e < 4; ++e) {
                int r = by * 128 + wm * 64 + mi * 16 + g + ((e >> 1) ? 8 : 0);
                int cg = bx * 128 + wn * 32 + ni * 8 + tg * 2 + (e & 1);
                float v = silu(acc[mi][ni][e] + pb[cg]);
                int s = r >> 2, b = r & 3;
                if (bx < 16) {
                    d_u[(size_t)r * HDIM + cg] = v;
                } else if (bx < 32) {
                    int h = cg - HDIM;
                    d_vT[((size_t)b * HDIM + h) * S_LEN + s] = v;
                } else {
                    int zi = cg - 2 * HDIM;
                    size_t qi = ((size_t)b * S_LEN + s) * ZDIM + zi;
                    d_q[qi]  = v * gamma[zi]        + beta[zi];
                    d_kk[qi] = v * gamma[ZDIM + zi] + beta[ZDIM + zi];
                }
            }
        }
    }
}

// ---------------------------------------------------------------------------
// K2: scores = relu(q k^T / S + bias)^2, causal (fp32 FFMA, small)
// ---------------------------------------------------------------------------
#define BK 16
__global__ void __launch_bounds__(NTHREADS, 2)
k_score(const float* __restrict__ rpb)
{
    const int by = blockIdx.y, bx = blockIdx.x, b = blockIdx.z;
    if (bx > by) return;
    __shared__ float As[BK][129];
    __shared__ float Bs[BK][129];
    float acc[8][8] = {};
    const float* Ag0 = d_q  + ((size_t)b * S_LEN + by * 128) * ZDIM;
    const float* Bg0 = d_kk + ((size_t)b * S_LEN + bx * 128) * ZDIM;
    const int tid = threadIdx.x;
    const int lr = tid >> 2, lc = (tid & 3) << 2;
    const float* Ag = Ag0 + lr * ZDIM + lc;
    const float* Bg = Bg0 + lr * ZDIM + lc;
    const int ty = tid >> 4, tx = tid & 15;
    for (int kk = 0; kk < ZDIM / BK; ++kk) {
        float4 a0 = *(const float4*)(Ag);
        float4 a1 = *(const float4*)(Ag + 64 * ZDIM);
        float4 b0 = *(const float4*)(Bg);
        float4 b1 = *(const float4*)(Bg + 64 * ZDIM);
        __syncthreads();
        As[lc + 0][lr] = a0.x; As[lc + 1][lr] = a0.y; As[lc + 2][lr] = a0.z; As[lc + 3][lr] = a0.w;
        As[lc + 0][lr + 64] = a1.x; As[lc + 1][lr + 64] = a1.y; As[lc + 2][lr + 64] = a1.z; As[lc + 3][lr + 64] = a1.w;
        Bs[lc + 0][lr] = b0.x; Bs[lc + 1][lr] = b0.y; Bs[lc + 2][lr] = b0.z; Bs[lc + 3][lr] = b0.w;
        Bs[lc + 0][lr + 64] = b1.x; Bs[lc + 1][lr + 64] = b1.y; Bs[lc + 2][lr + 64] = b1.z; Bs[lc + 3][lr + 64] = b1.w;
        __syncthreads();
#pragma unroll
        for (int k = 0; k < BK; ++k) {
            float ar[8], br[8];
#pragma unroll
            for (int i = 0; i < 8; ++i) ar[i] = As[k][i * 16 + ty];
#pragma unroll
            for (int j = 0; j < 8; ++j) br[j] = Bs[k][j * 16 + tx];
#pragma unroll
            for (int i = 0; i < 8; ++i)
#pragma unroll
                for (int j = 0; j < 8; ++j) acc[i][j] += ar[i] * br[j];
        }
        Ag += BK; Bg += BK;
    }
#pragma unroll
    for (int i = 0; i < 8; ++i) {
#pragma unroll
        for (int j = 0; j < 8; ++j) {
            int r = by * 128 + i * 16 + ty;
            int c = bx * 128 + j * 16 + tx;
            float v = acc[i][j] * (1.0f / (float)S_LEN) + rpb[(S_LEN - 1) + c - r];
            float a = (c > r) ? 0.0f : fmaxf(v, 0.0f);
            d_attn[((size_t)b * S_LEN + r) * S_LEN + c] = a * a;
        }
    }
}

// ---------------------------------------------------------------------------
// K3: g = (attn @ v) * u   (K truncated at diagonal)
// ---------------------------------------------------------------------------
__global__ void __launch_bounds__(NTHREADS, 1)
k_av_t()
{
    const int bx = blockIdx.x, by = blockIdx.y, b = blockIdx.z;
    float acc[4][4][4] = {};
    mma_gemm(d_attn + ((size_t)b * S_LEN + by * 128) * S_LEN, S_LEN,
             d_vT   + ((size_t)b * HDIM + bx * 128) * S_LEN, S_LEN,
             (by + 1) * 4, acc);

    const int lane = threadIdx.x & 31, wid = threadIdx.x >> 5;
    const int g = lane >> 2, tg = lane & 3;
    const int wm = wid & 1, wn = wid >> 1;
#pragma unroll
    for (int mi = 0; mi < 4; ++mi) {
#pragma unroll
        for (int ni = 0; ni < 4; ++ni) {
#pragma unroll
            for (int e = 0; e < 4; ++e) {
                int q = by * 128 + wm * 64 + mi * 16 + g + ((e >> 1) ? 8 : 0);
                int h = bx * 128 + wn * 32 + ni * 8 + tg * 2 + (e & 1);
                size_t idx = ((size_t)q * BSZ + b) * HDIM + h;
                d_g[idx] = acc[mi][ni][e] * d_u[idx];
            }
        }
    }
}

// ---------------------------------------------------------------------------
// K4: out = g @ Wo^T + bo
// ---------------------------------------------------------------------------
__global__ void __launch_bounds__(NTHREADS, 1)
k_out_t(const float* __restrict__ OW, const float* __restrict__ ob,
        float* __restrict__ out)
{
    const int bx = blockIdx.x, by = blockIdx.y;
    float acc[4][4][4] = {};
    mma_gemm(d_g + (size_t)by * 128 * HDIM, HDIM,
             OW + (size_t)bx * 128 * HDIM, HDIM, HDIM / 32, acc);

    const int lane = threadIdx.x & 31, wid = threadIdx.x >> 5;
    const int g = lane >> 2, tg = lane & 3;
    const int wm = wid & 1, wn = wid >> 1;
#pragma unroll
    for (int mi = 0; mi < 4; ++mi) {
#pragma unroll
        for (int ni = 0; ni < 4; ++ni) {
#pragma unroll
            for (int e = 0; e < 4; ++e) {
                int r = by * 128 + wm * 64 + mi * 16 + g + ((e >> 1) ? 8 : 0);
                int c = bx * 128 + wn * 32 + ni * 8 + tg * 2 + (e & 1);
                out[(size_t)r * EDIM + c] = acc[mi][ni][e] + ob[c];
            }
        }
    }
}

// ---------------------------------------------------------------------------
extern "C" void kernel_launch(void* const* d_in, const int* in_sizes, int n_in,
                              void* d_out, int out_size)
{
    const float* x      = (const float*)d_in[0];
    const float* proj_w = (const float*)d_in[2];
    const float* proj_b = (const float*)d_in[3];
    const float* out_w  = (const float*)d_in[4];
    const float* out_b  = (const float*)d_in[5];
    const float* gamma  = (const float*)d_in[6];
    const float* beta   = (const float*)d_in[7];
    const float* rpb    = (const float*)d_in[8];
    float* out = (float*)d_out;

    cudaFuncSetAttribute(k_proj_t, cudaFuncAttributeMaxDynamicSharedMemorySize, SMEM_DYN_BYTES);
    cudaFuncSetAttribute(k_av_t,   cudaFuncAttributeMaxDynamicSharedMemorySize, SMEM_DYN_BYTES);
    cudaFuncSetAttribute(k_out_t,  cudaFuncAttributeMaxDynamicSharedMemorySize, SMEM_DYN_BYTES);

    dim3 blk(NTHREADS);
    k_proj_t<<<dim3(33, 64), blk, SMEM_DYN_BYTES>>>(x, proj_w, proj_b, gamma, beta);
    k_score <<<dim3(16, 16, 4), blk>>>(rpb);
    k_av_t  <<<dim3(16, 16, 4), blk, SMEM_DYN_BYTES>>>();
    k_out_t <<<dim3(8, 64), blk, SMEM_DYN_BYTES>>>(out_w, out_b, out);
}

// round 10
// speedup vs baseline: 1.1151x; 1.1151x over previous
#include <cuda_runtime.h>
#include <cuda_bf16.h>
#include <cstdint>

// ---------------------------------------------------------------------------
// GatedAttentionUnit: S=2048, B=4, E=1024, Z=128, H=2048
// R10: R6 skeleton (single-buffer, 64-wide chunks, 69.6 KB smem — proven) +
//      fragment reuse in the inner loop: per ks load bh/bl/av once and issue
//      hh,hl,lh -> 48 LDS per 48 MMAs (was 72). smem kept well under the
//      ~100 KB container limit discovered in R7-R9.
//      Math unchanged: mma.sync bf16 split-2 (hh+hl+lh), fp32 accum.
// ---------------------------------------------------------------------------

#define S_LEN 2048
#define BSZ 4
#define EDIM 1024
#define ZDIM 128
#define HDIM 2048
#define NTHREADS 256

// smem tile: 128 rows x 128 bf16 (hi 64 | lo 64), row stride 68 words
// (68 % 32 == 4 -> fragment LDS bank == lane -> conflict-free)
#define ROW_W 68
#define TILE_W (128 * ROW_W)            // words per tile
#define SMEM_DYN_BYTES (2 * TILE_W * 4) // A + B = 69632 B

// Scratch (device globals: allocation-free per harness rules)
__device__ float d_u   [(size_t)S_LEN * BSZ * HDIM];
__device__ float d_vT  [(size_t)BSZ * HDIM * S_LEN];
__device__ float d_q   [(size_t)BSZ * S_LEN * ZDIM];
__device__ float d_kk  [(size_t)BSZ * S_LEN * ZDIM];
__device__ float d_attn[(size_t)BSZ * S_LEN * S_LEN];
__device__ float d_g   [(size_t)S_LEN * BSZ * HDIM];

// ---------------------------------------------------------------------------
__device__ __forceinline__ void mma16816(float* d, const uint32_t* a, const uint32_t* b) {
    asm volatile(
        "mma.sync.aligned.m16n8k16.row.col.f32.bf16.bf16.f32 "
        "{%0,%1,%2,%3}, {%4,%5,%6,%7}, {%8,%9}, {%0,%1,%2,%3};"
        : "+f"(d[0]), "+f"(d[1]), "+f"(d[2]), "+f"(d[3])
        : "r"(a[0]), "r"(a[1]), "r"(a[2]), "r"(a[3]), "r"(b[0]), "r"(b[1]));
}

__device__ __forceinline__ uint32_t pack_hi(float f0, float f1) {
    __nv_bfloat16 h0 = __float2bfloat16_rn(f0);
    __nv_bfloat16 h1 = __float2bfloat16_rn(f1);
    return (uint32_t)__bfloat16_as_ushort(h0) | ((uint32_t)__bfloat16_as_ushort(h1) << 16);
}
__device__ __forceinline__ uint32_t pack_lo(float f0, float f1) {
    __nv_bfloat16 h0 = __float2bfloat16_rn(f0);
    __nv_bfloat16 h1 = __float2bfloat16_rn(f1);
    __nv_bfloat16 l0 = __float2bfloat16_rn(f0 - __bfloat162float(h0));
    __nv_bfloat16 l1 = __float2bfloat16_rn(f1 - __bfloat162float(h1));
    return (uint32_t)__bfloat16_as_ushort(l0) | ((uint32_t)__bfloat16_as_ushort(l1) << 16);
}

// Load one 64-fp32-wide K chunk of A and B tiles into registers (8+8 float4)
__device__ __forceinline__ void load_chunk(
    const float* __restrict__ A, int lda,
    const float* __restrict__ B, int ldb, int c, float4 fs[16])
{
    const int tid = threadIdx.x;
#pragma unroll
    for (int u = 0; u < 4; ++u) {
        int idx = u * 256 + tid;
        int row = idx >> 3, grp = idx & 7;
        const float* pa = A + (size_t)row * lda + c * 64 + grp * 8;
        fs[u * 2 + 0] = *(const float4*)pa;
        fs[u * 2 + 1] = *(const float4*)(pa + 4);
        const float* pb = B + (size_t)row * ldb + c * 64 + grp * 8;
        fs[u * 2 + 8] = *(const float4*)pb;
        fs[u * 2 + 9] = *(const float4*)(pb + 4);
    }
}

// Convert registers -> [hi|lo] bf16 smem tiles
__device__ __forceinline__ void store_chunk(const float4 fs[16],
                                            uint32_t* Aw, uint32_t* Bw)
{
    const int tid = threadIdx.x;
#pragma unroll
    for (int u = 0; u < 4; ++u) {
        int idx = u * 256 + tid;
        int row = idx >> 3, grp = idx & 7;
        const float4 a0 = fs[u * 2 + 0], a1 = fs[u * 2 + 1];
        const float4 b0 = fs[u * 2 + 8], b1 = fs[u * 2 + 9];
        uint32_t* ah = Aw + row * ROW_W + grp * 4;
        *(uint4*)ah = make_uint4(pack_hi(a0.x, a0.y), pack_hi(a0.z, a0.w),
                                 pack_hi(a1.x, a1.y), pack_hi(a1.z, a1.w));
        *(uint4*)(ah + 32) = make_uint4(pack_lo(a0.x, a0.y), pack_lo(a0.z, a0.w),
                                        pack_lo(a1.x, a1.y), pack_lo(a1.z, a1.w));
        uint32_t* bh = Bw + row * ROW_W + grp * 4;
        *(uint4*)bh = make_uint4(pack_hi(b0.x, b0.y), pack_hi(b0.z, b0.w),
                                 pack_hi(b1.x, b1.y), pack_hi(b1.z, b1.w));
        *(uint4*)(bh + 32) = make_uint4(pack_lo(b0.x, b0.y), pack_lo(b0.z, b0.w),
                                        pack_lo(b1.x, b1.y), pack_lo(b1.z, b1.w));
    }
}

// ---------------------------------------------------------------------------
// Core GEMM: acc(128x128) = A(128xK) * B(128xK)^T, fp32 in, fp32 accum.
// Warp grid 2(M) x 4(N); per-warp 64x32 via 4x4 m16n8k16 tiles.
// Split-2 with fragment reuse: per ks load B-hi, B-lo, A-hi -> hh, hl;
// overwrite A-lo -> lh.  48 LDS / 48 MMA per ks-group.
// ---------------------------------------------------------------------------
extern __shared__ uint32_t smw[];

__device__ __forceinline__ void mma_gemm(
    const float* __restrict__ A, int lda,
    const float* __restrict__ B, int ldb,
    int nChunks, float acc[4][4][4])
{
    uint32_t* Aw = smw;
    uint32_t* Bw = smw + TILE_W;
    const int tid = threadIdx.x;
    const int lane = tid & 31, wid = tid >> 5;
    const int g = lane >> 2, tg = lane & 3;
    const int wm = wid & 1, wn = wid >> 1;
    const int arow = wm * 64 + g;
    const int brow = wn * 32 + g;

    float4 fs[16];
    load_chunk(A, lda, B, ldb, 0, fs);

    for (int c = 0; c < nChunks; ++c) {
        __syncthreads();
        store_chunk(fs, Aw, Bw);
        __syncthreads();
        if (c + 1 < nChunks) load_chunk(A, lda, B, ldb, c + 1, fs);

        // 4 ks-groups of K=16; per group: bh, bl, A-hi (hh, hl), A-lo (lh)
#pragma unroll 1
        for (int ks = 0; ks < 4; ++ks) {
            uint32_t bh[4][2], bl[4][2], av[4][4];
#pragma unroll
            for (int ni = 0; ni < 4; ++ni) {
                const uint32_t* pB = Bw + (brow + ni * 8) * ROW_W + ks * 8 + tg;
                bh[ni][0] = pB[0];
                bh[ni][1] = pB[4];
                bl[ni][0] = pB[32];
                bl[ni][1] = pB[36];
            }
#pragma unroll
            for (int mi = 0; mi < 4; ++mi) {
                const uint32_t* pA = Aw + (arow + mi * 16) * ROW_W + ks * 8 + tg;
                av[mi][0] = pA[0];
                av[mi][1] = pA[8 * ROW_W];
                av[mi][2] = pA[4];
                av[mi][3] = pA[8 * ROW_W + 4];
            }
#pragma unroll
            for (int mi = 0; mi < 4; ++mi)
#pragma unroll
                for (int ni = 0; ni < 4; ++ni)
                    mma16816(acc[mi][ni], av[mi], bh[ni]);
#pragma unroll
            for (int mi = 0; mi < 4; ++mi)
#pragma unroll
                for (int ni = 0; ni < 4; ++ni)
                    mma16816(acc[mi][ni], av[mi], bl[ni]);
#pragma unroll
            for (int mi = 0; mi < 4; ++mi) {
                const uint32_t* pA = Aw + (arow + mi * 16) * ROW_W + 32 + ks * 8 + tg;
                av[mi][0] = pA[0];
                av[mi][1] = pA[8 * ROW_W];
                av[mi][2] = pA[4];
                av[mi][3] = pA[8 * ROW_W + 4];
            }
#pragma unroll
            for (int mi = 0; mi < 4; ++mi)
#pragma unroll
                for (int ni = 0; ni < 4; ++ni)
                    mma16816(acc[mi][ni], av[mi], bh[ni]);
        }
    }
}

__device__ __forceinline__ float silu(float v) { return v / (1.0f + __expf(-v)); }

// Per-thread element coordinates inside the 128x128 tile:
//   r = wm*64 + mi*16 + g + (e>=2 ? 8 : 0)
//   c = wn*32 + ni*8 + tg*2 + (e&1)

// ---------------------------------------------------------------------------
// K1: proj = silu(x @ Wp^T + bp); split into u / vT / q / k
// ---------------------------------------------------------------------------
__global__ void __launch_bounds__(NTHREADS, 1)
k_proj_t(const float* __restrict__ X, const float* __restrict__ W,
         const float* __restrict__ pb, const float* __restrict__ gamma,
         const float* __restrict__ beta)
{
    const int bx = blockIdx.x, by = blockIdx.y;
    float acc[4][4][4] = {};
    mma_gemm(X + (size_t)by * 128 * EDIM, EDIM,
             W + (size_t)bx * 128 * EDIM, EDIM, EDIM / 64, acc);

    const int lane = threadIdx.x & 31, wid = threadIdx.x >> 5;
    const int g = lane >> 2, tg = lane & 3;
    const int wm = wid & 1, wn = wid >> 1;
#pragma unroll
    for (int mi = 0; mi < 4; ++mi) {
#pragma unroll
        for (int ni = 0; ni < 4; ++ni) {
#pragma unroll
            for (int e = 0; e < 4; ++e) {
                int r = by * 128 + wm * 64 + mi * 16 + g + ((e >> 1) ? 8 : 0);
                int cg = bx * 128 + wn * 32 + ni * 8 + tg * 2 + (e & 1);
                float v = silu(acc[mi][ni][e] + pb[cg]);
                int s = r >> 2, b = r & 3;
                if (bx < 16) {
                    d_u[(size_t)r * HDIM + cg] = v;
                } else if (bx < 32) {
                    int h = cg - HDIM;
                    d_vT[((size_t)b * HDIM + h) * S_LEN + s] = v;
                } else {
                    int zi = cg - 2 * HDIM;
                    size_t qi = ((size_t)b * S_LEN + s) * ZDIM + zi;
                    d_q[qi]  = v * gamma[zi]        + beta[zi];
                    d_kk[qi] = v * gamma[ZDIM + zi] + beta[ZDIM + zi];
                }
            }
        }
    }
}

// ---------------------------------------------------------------------------
// K2: scores = relu(q k^T / S + bias)^2, causal (fp32 FFMA, small)
// ---------------------------------------------------------------------------
#define BK 16
__global__ void __launch_bounds__(NTHREADS, 2)
k_score(const float* __restrict__ rpb)
{
    const int by = blockIdx.y, bx = blockIdx.x, b = blockIdx.z;
    if (bx > by) return;
    __shared__ float As[BK][129];
    __shared__ float Bs[BK][129];
    float acc[8][8] = {};
    const float* Ag0 = d_q  + ((size_t)b * S_LEN + by * 128) * ZDIM;
    const float* Bg0 = d_kk + ((size_t)b * S_LEN + bx * 128) * ZDIM;
    const int tid = threadIdx.x;
    const int lr = tid >> 2, lc = (tid & 3) << 2;
    const float* Ag = Ag0 + lr * ZDIM + lc;
    const float* Bg = Bg0 + lr * ZDIM + lc;
    const int ty = tid >> 4, tx = tid & 15;
    for (int kk = 0; kk < ZDIM / BK; ++kk) {
        float4 a0 = *(const float4*)(Ag);
        float4 a1 = *(const float4*)(Ag + 64 * ZDIM);
        float4 b0 = *(const float4*)(Bg);
        float4 b1 = *(const float4*)(Bg + 64 * ZDIM);
        __syncthreads();
        As[lc + 0][lr] = a0.x; As[lc + 1][lr] = a0.y; As[lc + 2][lr] = a0.z; As[lc + 3][lr] = a0.w;
        As[lc + 0][lr + 64] = a1.x; As[lc + 1][lr + 64] = a1.y; As[lc + 2][lr + 64] = a1.z; As[lc + 3][lr + 64] = a1.w;
        Bs[lc + 0][lr] = b0.x; Bs[lc + 1][lr] = b0.y; Bs[lc + 2][lr] = b0.z; Bs[lc + 3][lr] = b0.w;
        Bs[lc + 0][lr + 64] = b1.x; Bs[lc + 1][lr + 64] = b1.y; Bs[lc + 2][lr + 64] = b1.z; Bs[lc + 3][lr + 64] = b1.w;
        __syncthreads();
#pragma unroll
        for (int k = 0; k < BK; ++k) {
            float ar[8], br[8];
#pragma unroll
            for (int i = 0; i < 8; ++i) ar[i] = As[k][i * 16 + ty];
#pragma unroll
            for (int j = 0; j < 8; ++j) br[j] = Bs[k][j * 16 + tx];
#pragma unroll
            for (int i = 0; i < 8; ++i)
#pragma unroll
                for (int j = 0; j < 8; ++j) acc[i][j] += ar[i] * br[j];
        }
        Ag += BK; Bg += BK;
    }
#pragma unroll
    for (int i = 0; i < 8; ++i) {
#pragma unroll
        for (int j = 0; j < 8; ++j) {
            int r = by * 128 + i * 16 + ty;
            int c = bx * 128 + j * 16 + tx;
            float v = acc[i][j] * (1.0f / (float)S_LEN) + rpb[(S_LEN - 1) + c - r];
            float a = (c > r) ? 0.0f : fmaxf(v, 0.0f);
            d_attn[((size_t)b * S_LEN + r) * S_LEN + c] = a * a;
        }
    }
}

// ---------------------------------------------------------------------------
// K3: g = (attn @ v) * u   (K truncated at diagonal)
// ---------------------------------------------------------------------------
__global__ void __launch_bounds__(NTHREADS, 1)
k_av_t()
{
    const int bx = blockIdx.x, by = blockIdx.y, b = blockIdx.z;
    float acc[4][4][4] = {};
    mma_gemm(d_attn + ((size_t)b * S_LEN + by * 128) * S_LEN, S_LEN,
             d_vT   + ((size_t)b * HDIM + bx * 128) * S_LEN, S_LEN,
             (by + 1) * 2, acc);

    const int lane = threadIdx.x & 31, wid = threadIdx.x >> 5;
    const int g = lane >> 2, tg = lane & 3;
    const int wm = wid & 1, wn = wid >> 1;
#pragma unroll
    for (int mi = 0; mi < 4; ++mi) {
#pragma unroll
        for (int ni = 0; ni < 4; ++ni) {
#pragma unroll
            for (int e = 0; e < 4; ++e) {
                int q = by * 128 + wm * 64 + mi * 16 + g + ((e >> 1) ? 8 : 0);
                int h = bx * 128 + wn * 32 + ni * 8 + tg * 2 + (e & 1);
                size_t idx = ((size_t)q * BSZ + b) * HDIM + h;
                d_g[idx] = acc[mi][ni][e] * d_u[idx];
            }
        }
    }
}

// ---------------------------------------------------------------------------
// K4: out = g @ Wo^T + bo
// ---------------------------------------------------------------------------
__global__ void __launch_bounds__(NTHREADS, 1)
k_out_t(const float* __restrict__ OW, const float* __restrict__ ob,
        float* __restrict__ out)
{
    const int bx = blockIdx.x, by = blockIdx.y;
    float acc[4][4][4] = {};
    mma_gemm(d_g + (size_t)by * 128 * HDIM, HDIM,
             OW + (size_t)bx * 128 * HDIM, HDIM, HDIM / 64, acc);

    const int lane = threadIdx.x & 31, wid = threadIdx.x >> 5;
    const int g = lane >> 2, tg = lane & 3;
    const int wm = wid & 1, wn = wid >> 1;
#pragma unroll
    for (int mi = 0; mi < 4; ++mi) {
#pragma unroll
        for (int ni = 0; ni < 4; ++ni) {
#pragma unroll
            for (int e = 0; e < 4; ++e) {
                int r = by * 128 + wm * 64 + mi * 16 + g + ((e >> 1) ? 8 : 0);
                int c = bx * 128 + wn * 32 + ni * 8 + tg * 2 + (e & 1);
                out[(size_t)r * EDIM + c] = acc[mi][ni][e] + ob[c];
            }
        }
    }
}

// ---------------------------------------------------------------------------
extern "C" void kernel_launch(void* const* d_in, const int* in_sizes, int n_in,
                              void* d_out, int out_size)
{
    const float* x      = (const float*)d_in[0];
    const float* proj_w = (const float*)d_in[2];
    const float* proj_b = (const float*)d_in[3];
    const float* out_w  = (const float*)d_in[4];
    const float* out_b  = (const float*)d_in[5];
    const float* gamma  = (const float*)d_in[6];
    const float* beta   = (const float*)d_in[7];
    const float* rpb    = (const float*)d_in[8];
    float* out = (float*)d_out;

    cudaFuncSetAttribute(k_proj_t, cudaFuncAttributeMaxDynamicSharedMemorySize, SMEM_DYN_BYTES);
    cudaFuncSetAttribute(k_av_t,   cudaFuncAttributeMaxDynamicSharedMemorySize, SMEM_DYN_BYTES);
    cudaFuncSetAttribute(k_out_t,  cudaFuncAttributeMaxDynamicSharedMemorySize, SMEM_DYN_BYTES);

    dim3 blk(NTHREADS);
    k_proj_t<<<dim3(33, 64), blk, SMEM_DYN_BYTES>>>(x, proj_w, proj_b, gamma, beta);
    k_score <<<dim3(16, 16, 4), blk>>>(rpb);
    k_av_t  <<<dim3(16, 16, 4), blk, SMEM_DYN_BYTES>>>();
    k_out_t <<<dim3(8, 64), blk, SMEM_DYN_BYTES>>>(out_w, out_b, out);
}